// round 8
// baseline (speedup 1.0000x reference)
#include <cuda_runtime.h>
#include <cuda_bf16.h>
#include <cstdint>
#include <cstddef>

#define NN 100000
#define EMAX 1600000
#define TILES 782          // ceil(NN/128)

// ---- static device scratch ----
__device__ int      g_count[NN];
__device__ int      g_offsets[NN + 1];
__device__ int      g_cursor[NN];
__device__ int      g_sorted[EMAX];
__device__ uint2    g_xh[(size_t)NN * 32];     // x as bf16 plane (gather source, layer 1)
__device__ uint2    g_h1h[(size_t)NN * 32];    // h1 as bf16 plane (gather source, layer 2)
__device__ uint2    g_mh[(size_t)NN * 32];     // mean hi plane (bf16)
__device__ uint2    g_ml[(size_t)NN * 32];     // mean lo plane (bf16 residual)
__device__ float    g_h1[(size_t)NN * 128];    // h1 fp32 (A1 for layer-2 GEMM)
__device__ uint32_t g_bp1[32768];   // fragment-order packed B (hi/lo bf16x2), 128KB
__device__ uint32_t g_bp2[32768];

// ===================== CSR build =====================
__global__ void zero_count_kernel() {
    int i = blockIdx.x * blockDim.x + threadIdx.x;
    if (i < NN) g_count[i] = 0;
}
__global__ void hist_kernel(const int* __restrict__ dst, int E) {
    for (int e = blockIdx.x * blockDim.x + threadIdx.x; e < E; e += gridDim.x * blockDim.x)
        atomicAdd(&g_count[dst[e]], 1);
}
// single-block serial-chunk scan: 1024 threads x 98 elements each
__global__ void scan_fused_kernel() {
    const int CH = 98;   // 1024*98 = 100352 >= NN
    __shared__ int ws[32];
    int t = threadIdx.x, lane = t & 31, w = t >> 5;
    int beg = t * CH, end = beg + CH < NN ? beg + CH : NN;
    int s = 0;
    for (int i = beg; i < end; i++) s += g_count[i];
    // block exclusive scan of per-thread sums
    int x = s;
    #pragma unroll
    for (int o = 1; o < 32; o <<= 1) { int y = __shfl_up_sync(~0u, x, o); if (lane >= o) x += y; }
    if (lane == 31) ws[w] = x;
    __syncthreads();
    if (w == 0) {
        int v = ws[lane];
        #pragma unroll
        for (int o = 1; o < 32; o <<= 1) { int y = __shfl_up_sync(~0u, v, o); if (lane >= o) v += y; }
        ws[lane] = v;
    }
    __syncthreads();
    int run = (w ? ws[w - 1] : 0) + x - s;   // exclusive prefix for this thread's chunk
    for (int i = beg; i < end; i++) {
        int v = g_count[i];
        g_offsets[i] = run;
        g_cursor[i] = run;
        run += v;
    }
    if (t == 1023) g_offsets[NN] = run;      // last chunk empty -> run == grand total
}
__global__ void scatter_kernel(const int* __restrict__ src, const int* __restrict__ dst, int E) {
    for (int e = blockIdx.x * blockDim.x + threadIdx.x; e < E; e += gridDim.x * blockDim.x) {
        int d = dst[e];
        int pos = atomicAdd(&g_cursor[d], 1);
        g_sorted[pos] = src[e];
    }
}

// ===================== fp32 -> bf16 plane =====================
__global__ void tobf16_kernel(const float4* __restrict__ x4, uint2* __restrict__ xh, int n4) {
    int i = blockIdx.x * blockDim.x + threadIdx.x;
    if (i >= n4) return;
    float4 v = x4[i];
    __nv_bfloat162 a = __float22bfloat162_rn(make_float2(v.x, v.y));
    __nv_bfloat162 b = __float22bfloat162_rn(make_float2(v.z, v.w));
    xh[i] = make_uint2(*(uint32_t*)&a, *(uint32_t*)&b);
}

// ===================== B fragment pack (FULL N=128) =====================
__global__ void pack_bp_kernel(const float* __restrict__ wl, const float* __restrict__ wr,
                               uint32_t* __restrict__ bp) {
    int idx = blockIdx.x * blockDim.x + threadIdx.x;
    if (idx >= 32768) return;
    int j = idx & 3, lane = (idx >> 2) & 31, p = (idx >> 7) & 1;
    int nw = (idx >> 8) & 3, term = (idx >> 10) & 1, gk = idx >> 11;
    int nb = p * 2 + (j >> 1), reg = j & 1;
    int n = nw * 32 + nb * 8 + (lane >> 2);
    int k = gk * 16 + reg * 8 + 2 * (lane & 3);
    float v0 = (k < 128) ? wl[n * 128 + k] : wr[n * 128 + (k - 128)];
    float v1 = (k + 1 < 128) ? wl[n * 128 + k + 1] : wr[n * 128 + (k + 1 - 128)];
    __nv_bfloat162 h2 = __float22bfloat162_rn(make_float2(v0, v1));
    if (term == 0) {
        bp[idx] = *(uint32_t*)&h2;
    } else {
        float r0 = v0 - __low2float(h2);
        float r1 = v1 - __high2float(h2);
        __nv_bfloat162 l2 = __float22bfloat162_rn(make_float2(r0, r1));
        bp[idx] = *(uint32_t*)&l2;
    }
}

// ===================== aggregation (bf16 gather -> mean hi/lo planes) =====================
__global__ void agg_kernel(const uint2* __restrict__ xp, uint2* __restrict__ mh,
                           uint2* __restrict__ ml) {
    int gw = (blockIdx.x * blockDim.x + threadIdx.x) >> 5;
    int lane = threadIdx.x & 31;
    if (gw >= NN) return;
    int beg = g_offsets[gw], end = g_offsets[gw + 1];
    float a0 = 0.f, a1 = 0.f, a2 = 0.f, a3 = 0.f;
    int p = beg;
    for (; p + 4 <= end; p += 4) {
        int s0 = g_sorted[p], s1 = g_sorted[p + 1], s2 = g_sorted[p + 2], s3 = g_sorted[p + 3];
        uint2 u0 = __ldg(&xp[(size_t)s0 * 32 + lane]);
        uint2 u1 = __ldg(&xp[(size_t)s1 * 32 + lane]);
        uint2 u2 = __ldg(&xp[(size_t)s2 * 32 + lane]);
        uint2 u3 = __ldg(&xp[(size_t)s3 * 32 + lane]);
        float2 f;
        f = __bfloat1622float2(*(__nv_bfloat162*)&u0.x); a0 += f.x; a1 += f.y;
        f = __bfloat1622float2(*(__nv_bfloat162*)&u0.y); a2 += f.x; a3 += f.y;
        f = __bfloat1622float2(*(__nv_bfloat162*)&u1.x); a0 += f.x; a1 += f.y;
        f = __bfloat1622float2(*(__nv_bfloat162*)&u1.y); a2 += f.x; a3 += f.y;
        f = __bfloat1622float2(*(__nv_bfloat162*)&u2.x); a0 += f.x; a1 += f.y;
        f = __bfloat1622float2(*(__nv_bfloat162*)&u2.y); a2 += f.x; a3 += f.y;
        f = __bfloat1622float2(*(__nv_bfloat162*)&u3.x); a0 += f.x; a1 += f.y;
        f = __bfloat1622float2(*(__nv_bfloat162*)&u3.y); a2 += f.x; a3 += f.y;
    }
    for (; p < end; p++) {
        int s = g_sorted[p];
        uint2 u = __ldg(&xp[(size_t)s * 32 + lane]);
        float2 f;
        f = __bfloat1622float2(*(__nv_bfloat162*)&u.x); a0 += f.x; a1 += f.y;
        f = __bfloat1622float2(*(__nv_bfloat162*)&u.y); a2 += f.x; a3 += f.y;
    }
    float inv = (end > beg) ? 1.0f / (float)(end - beg) : 0.0f;
    a0 *= inv; a1 *= inv; a2 *= inv; a3 *= inv;
    // split into hi + lo bf16 planes (hi+lo ~ exact to 2^-18)
    __nv_bfloat162 h01 = __float22bfloat162_rn(make_float2(a0, a1));
    __nv_bfloat162 h23 = __float22bfloat162_rn(make_float2(a2, a3));
    float2 hf01 = __bfloat1622float2(h01), hf23 = __bfloat1622float2(h23);
    __nv_bfloat162 l01 = __float22bfloat162_rn(make_float2(a0 - hf01.x, a1 - hf01.y));
    __nv_bfloat162 l23 = __float22bfloat162_rn(make_float2(a2 - hf23.x, a3 - hf23.y));
    size_t oi = (size_t)gw * 32 + lane;
    mh[oi] = make_uint2(*(uint32_t*)&h01, *(uint32_t*)&h23);
    ml[oi] = make_uint2(*(uint32_t*)&l01, *(uint32_t*)&l23);
}

// ===================== mma.sync GEMM =====================
// MODE 0: C fp32 + bf16 hi-plane out.  MODE 1: fused outproj (out[n][4]).
#define AROW 144
#define SM_AHI  0
#define SM_ALO  18432
#define SM_BIAS 36864
#define SM_WOUT 37376
#define SM_RACC 39424
#define GEMM_SMEM 41472

__device__ __forceinline__ uint32_t smem_u32(const void* p) {
    uint32_t a;
    asm("{ .reg .u64 t; cvta.to.shared.u64 t, %1; cvt.u32.u64 %0, t; }" : "=r"(a) : "l"(p));
    return a;
}
__device__ __forceinline__ void ldm_x4(uint32_t* r, uint32_t addr) {
    asm volatile("ldmatrix.sync.aligned.m8n8.x4.shared.b16 {%0,%1,%2,%3}, [%4];"
                 : "=r"(r[0]), "=r"(r[1]), "=r"(r[2]), "=r"(r[3]) : "r"(addr));
}
__device__ __forceinline__ void mma_bf16(float* d, const uint32_t* a, uint32_t b0, uint32_t b1) {
    asm volatile("mma.sync.aligned.m16n8k16.row.col.f32.bf16.bf16.f32 "
                 "{%0,%1,%2,%3}, {%4,%5,%6,%7}, {%8,%9}, {%0,%1,%2,%3};"
                 : "+f"(d[0]), "+f"(d[1]), "+f"(d[2]), "+f"(d[3])
                 : "r"(a[0]), "r"(a[1]), "r"(a[2]), "r"(a[3]), "r"(b0), "r"(b1));
}

template <int MODE>
__global__ __launch_bounds__(256, 2) void gemm_mma_kernel(
    const uint2* __restrict__ Mh, const uint2* __restrict__ Ml,   // mean planes (A0)
    const float* __restrict__ A1,                                  // fp32 root term
    const uint32_t* __restrict__ Bp, const float* __restrict__ bias,
    float* __restrict__ C, uint32_t* __restrict__ Chp,             // MODE0 outputs
    const float* __restrict__ wout, const float* __restrict__ bout,
    float* __restrict__ Out)                                       // MODE1 output
{
    extern __shared__ char smem[];
    uint32_t sb = smem_u32(smem);
    int t = threadIdx.x, wid = t >> 5, lane = t & 31;
    int mw = wid >> 2, nw = wid & 3;      // warp grid 2 x 4

    if (t < 128) ((float*)(smem + SM_BIAS))[t] = bias[t];
    if (MODE == 1) {
        for (int i = t; i < 512; i += 256) ((float*)(smem + SM_WOUT))[i] = wout[i];
    }

    int frow = t >> 1, fh = t & 1;
    int lrow = (lane & 7) + ((lane >> 3) & 1) * 8;
    int lkb  = (lane >> 4) * 16;
    const float* bsm = (const float*)(smem + SM_BIAS);
    const float* wsm = (const float*)(smem + SM_WOUT);
    float* racc = (float*)(smem + SM_RACC);
    const uint4* bfrag = (const uint4*)(Bp) + ((nw * 2) * 128 + lane * 4) / 4;

    for (int tile = blockIdx.x; tile < TILES; tile += gridDim.x) {
        float acc[4][4][4];
        #pragma unroll
        for (int m = 0; m < 4; m++)
            #pragma unroll
            for (int nb = 0; nb < 4; nb++)
                #pragma unroll
                for (int r = 0; r < 4; r++) acc[m][nb][r] = 0.f;
        if (MODE == 1) {
            for (int i = t; i < 512; i += 256) racc[i] = 0.f;
        }

        int grow = tile * 128 + frow;
        bool rv = grow < NN;

        #pragma unroll 1
        for (int c = 0; c < 4; c++) {            // K chunks of 64
            __syncthreads();                     // prev chunk's ldmatrix done (+racc zero vis)
            // ---- fill A chunk ----
            char* hb = smem + SM_AHI + frow * AROW + fh * 64;
            char* lb = smem + SM_ALO + frow * AROW + fh * 64;
            if (c < 2) {
                // A0 from pre-split bf16 planes: direct copy, no conversion
                const char* hsrc = (const char*)Mh + (size_t)grow * 256 + c * 128 + fh * 64;
                const char* lsrc = (const char*)Ml + (size_t)grow * 256 + c * 128 + fh * 64;
                uint4 hv[4], lv[4];
                if (rv) {
                    #pragma unroll
                    for (int q = 0; q < 4; q++) {
                        hv[q] = __ldg((const uint4*)hsrc + q);
                        lv[q] = __ldg((const uint4*)lsrc + q);
                    }
                } else {
                    #pragma unroll
                    for (int q = 0; q < 4; q++) hv[q] = lv[q] = make_uint4(0, 0, 0, 0);
                }
                #pragma unroll
                for (int q = 0; q < 4; q++) {
                    *(uint4*)(hb + q * 16) = hv[q];
                    *(uint4*)(lb + q * 16) = lv[q];
                }
            } else {
                // A1 fp32 -> bf16 hi/lo split
                const float4* ap = (const float4*)A1 + (size_t)grow * 32 + ((c & 1) * 16 + fh * 8);
                float4 v[8];
                if (rv) {
                    #pragma unroll
                    for (int i = 0; i < 8; i++) v[i] = __ldg(ap + i);
                } else {
                    #pragma unroll
                    for (int i = 0; i < 8; i++) v[i] = make_float4(0.f, 0.f, 0.f, 0.f);
                }
                const float* vf = (const float*)v;
                uint32_t hw[16], lw[16];
                #pragma unroll
                for (int i = 0; i < 16; i++) {
                    float f0 = vf[2 * i], f1 = vf[2 * i + 1];
                    __nv_bfloat162 h2 = __float22bfloat162_rn(make_float2(f0, f1));
                    float r0 = f0 - __low2float(h2);
                    float r1 = f1 - __high2float(h2);
                    __nv_bfloat162 l2 = __float22bfloat162_rn(make_float2(r0, r1));
                    hw[i] = *(uint32_t*)&h2;
                    lw[i] = *(uint32_t*)&l2;
                }
                #pragma unroll
                for (int q = 0; q < 4; q++) {
                    *(uint4*)(hb + q * 16) = make_uint4(hw[4*q], hw[4*q+1], hw[4*q+2], hw[4*q+3]);
                    *(uint4*)(lb + q * 16) = make_uint4(lw[4*q], lw[4*q+1], lw[4*q+2], lw[4*q+3]);
                }
            }
            __syncthreads();
            // ---- compute: 4 k16-steps ----
            #pragma unroll
            for (int ks = 0; ks < 4; ks++) {
                int gk = c * 4 + ks;
                const uint4* bgk = bfrag + (size_t)gk * 512;
                uint4 bh0 = __ldg(bgk + 0);
                uint4 bh1 = __ldg(bgk + 32);
                uint4 bl0 = __ldg(bgk + 256);
                uint4 bl1 = __ldg(bgk + 288);
                uint32_t bh[4][2] = {{bh0.x, bh0.y}, {bh0.z, bh0.w}, {bh1.x, bh1.y}, {bh1.z, bh1.w}};
                uint32_t bl[4][2] = {{bl0.x, bl0.y}, {bl0.z, bl0.w}, {bl1.x, bl1.y}, {bl1.z, bl1.w}};
                #pragma unroll
                for (int m = 0; m < 4; m++) {
                    uint32_t ah[4], al[4];
                    uint32_t rbase = sb + (uint32_t)((mw * 64 + m * 16 + lrow) * AROW + ks * 32 + lkb);
                    ldm_x4(ah, rbase + SM_AHI);
                    ldm_x4(al, rbase + SM_ALO);
                    #pragma unroll
                    for (int nb = 0; nb < 4; nb++) {
                        mma_bf16(acc[m][nb], ah, bh[nb][0], bh[nb][1]);
                        mma_bf16(acc[m][nb], al, bh[nb][0], bh[nb][1]);
                        mma_bf16(acc[m][nb], ah, bl[nb][0], bl[nb][1]);
                    }
                }
            }
        }
        // ---- epilogue ----
        if (MODE == 0) {
            #pragma unroll
            for (int m = 0; m < 4; m++) {
                int orow0 = tile * 128 + mw * 64 + m * 16 + (lane >> 2);
                #pragma unroll
                for (int nb = 0; nb < 4; nb++) {
                    int ocol = nw * 32 + nb * 8 + 2 * (lane & 3);
                    float b0 = bsm[ocol], b1 = bsm[ocol + 1];
                    if (orow0 < NN) {
                        float2 o = make_float2(fmaxf(acc[m][nb][0] + b0, 0.f),
                                               fmaxf(acc[m][nb][1] + b1, 0.f));
                        *(float2*)&C[(size_t)orow0 * 128 + ocol] = o;
                        __nv_bfloat162 hp = __float22bfloat162_rn(o);
                        Chp[(size_t)orow0 * 64 + (ocol >> 1)] = *(uint32_t*)&hp;
                    }
                    if (orow0 + 8 < NN) {
                        float2 o = make_float2(fmaxf(acc[m][nb][2] + b0, 0.f),
                                               fmaxf(acc[m][nb][3] + b1, 0.f));
                        *(float2*)&C[(size_t)(orow0 + 8) * 128 + ocol] = o;
                        __nv_bfloat162 hp = __float22bfloat162_rn(o);
                        Chp[(size_t)(orow0 + 8) * 64 + (ocol >> 1)] = *(uint32_t*)&hp;
                    }
                }
            }
        } else {
            // fused outproj: out[r][j] = sum_c relu(acc+bias)[r][c] * wout[j][c] + bout[j]
            #pragma unroll
            for (int m = 0; m < 4; m++) {
                float pj0[4] = {0.f, 0.f, 0.f, 0.f};
                float pj1[4] = {0.f, 0.f, 0.f, 0.f};
                #pragma unroll
                for (int nb = 0; nb < 4; nb++) {
                    int ocol = nw * 32 + nb * 8 + 2 * (lane & 3);
                    float b0 = bsm[ocol], b1 = bsm[ocol + 1];
                    float v0 = fmaxf(acc[m][nb][0] + b0, 0.f);
                    float v1 = fmaxf(acc[m][nb][1] + b1, 0.f);
                    float v2 = fmaxf(acc[m][nb][2] + b0, 0.f);
                    float v3 = fmaxf(acc[m][nb][3] + b1, 0.f);
                    #pragma unroll
                    for (int j = 0; j < 4; j++) {
                        float w0 = wsm[j * 128 + ocol], w1 = wsm[j * 128 + ocol + 1];
                        pj0[j] += v0 * w0 + v1 * w1;
                        pj1[j] += v2 * w0 + v3 * w1;
                    }
                }
                #pragma unroll
                for (int j = 0; j < 4; j++) {
                    pj0[j] += __shfl_xor_sync(~0u, pj0[j], 1);
                    pj0[j] += __shfl_xor_sync(~0u, pj0[j], 2);
                    pj1[j] += __shfl_xor_sync(~0u, pj1[j], 1);
                    pj1[j] += __shfl_xor_sync(~0u, pj1[j], 2);
                }
                if ((lane & 3) == 0) {
                    int lr = mw * 64 + m * 16 + (lane >> 2);
                    #pragma unroll
                    for (int j = 0; j < 4; j++) {
                        atomicAdd(&racc[lr * 4 + j], pj0[j]);
                        atomicAdd(&racc[(lr + 8) * 4 + j], pj1[j]);
                    }
                }
            }
            __syncthreads();
            if (t < 128) {
                int orow = tile * 128 + t;
                if (orow < NN) {
                    float4 o;
                    o.x = racc[t * 4 + 0] + __ldg(&bout[0]);
                    o.y = racc[t * 4 + 1] + __ldg(&bout[1]);
                    o.z = racc[t * 4 + 2] + __ldg(&bout[2]);
                    o.w = racc[t * 4 + 3] + __ldg(&bout[3]);
                    *(float4*)&Out[(size_t)orow * 4] = o;
                }
            }
            __syncthreads();   // protect racc re-zero next tile
        }
    }
}

// ===================== launch =====================
extern "C" void kernel_launch(void* const* d_in, const int* in_sizes, int n_in,
                              void* d_out, int out_size) {
    const float* x    = (const float*)d_in[0];
    const int*   ei   = (const int*)d_in[1];
    const float* w1l  = (const float*)d_in[2];
    const float* b1l  = (const float*)d_in[3];
    const float* w1r  = (const float*)d_in[4];
    const float* w2l  = (const float*)d_in[5];
    const float* b2l  = (const float*)d_in[6];
    const float* w2r  = (const float*)d_in[7];
    const float* wout = (const float*)d_in[8];
    const float* bout = (const float*)d_in[9];
    float* out = (float*)d_out;

    int E = in_sizes[1] / 2;
    const int* src = ei;
    const int* dst = ei + E;

    uint2 *xh, *h1h, *mh, *ml;
    float *h1;
    uint32_t *bp1, *bp2;
    cudaGetSymbolAddress((void**)&xh, g_xh);
    cudaGetSymbolAddress((void**)&h1h, g_h1h);
    cudaGetSymbolAddress((void**)&mh, g_mh);
    cudaGetSymbolAddress((void**)&ml, g_ml);
    cudaGetSymbolAddress((void**)&h1, g_h1);
    cudaGetSymbolAddress((void**)&bp1, g_bp1);
    cudaGetSymbolAddress((void**)&bp2, g_bp2);

    cudaFuncSetAttribute(gemm_mma_kernel<0>, cudaFuncAttributeMaxDynamicSharedMemorySize, GEMM_SMEM);
    cudaFuncSetAttribute(gemm_mma_kernel<1>, cudaFuncAttributeMaxDynamicSharedMemorySize, GEMM_SMEM);

    // CSR build (counting sort by dst)
    zero_count_kernel<<<(NN + 255) / 256, 256>>>();
    hist_kernel<<<2048, 256>>>(dst, E);
    scan_fused_kernel<<<1, 1024>>>();
    scatter_kernel<<<2048, 256>>>(src, dst, E);

    // fragment-order bf16-split weight images (full N)
    pack_bp_kernel<<<128, 256>>>(w1l, w1r, bp1);
    pack_bp_kernel<<<128, 256>>>(w2l, w2r, bp2);

    // x -> bf16 plane for gather
    int n4 = NN * 32;
    tobf16_kernel<<<(n4 + 255) / 256, 256>>>((const float4*)x, xh, n4);

    int aggBlocks = (NN * 32 + 255) / 256;

    // layer 1
    agg_kernel<<<aggBlocks, 256>>>(xh, mh, ml);
    gemm_mma_kernel<0><<<296, 256, GEMM_SMEM>>>(mh, ml, x, bp1, b1l,
                                                h1, (uint32_t*)h1h, nullptr, nullptr, nullptr);
    // layer 2 (+ fused output projection)
    agg_kernel<<<aggBlocks, 256>>>(h1h, mh, ml);
    gemm_mma_kernel<1><<<296, 256, GEMM_SMEM>>>(mh, ml, h1, bp2, b2l,
                                                nullptr, nullptr, wout, bout, out);
}